// round 4
// baseline (speedup 1.0000x reference)
#include <cuda_runtime.h>

#define NIN     64
#define NOUT    64
#define NJ      (NIN * NOUT)       // 4096
#define NKNOTS  10
#define NBASIS  6
#define BATCH_TILE 14
#define THREADS 512
#define OHALF   32                 // o-values per block

// L2-resident accumulator for sum_b |spl[b, j]| + completion ticket.
// Zero-initialized at module load; the last block resets them each launch,
// so every graph replay sees zeros (deterministic).
__device__ float        g_splacc[NJ];
__device__ unsigned int g_ticket;

__global__ __launch_bounds__(THREADS, 2)
void kan_fused_kernel(const float* __restrict__ x,
                      const float* __restrict__ c_basis,
                      const float* __restrict__ c_spl,
                      const float* __restrict__ c_res,
                      const float* __restrict__ grid,
                      float* __restrict__ y_out,
                      float* __restrict__ reg_out,
                      int batch, float inv_batch, int nblocks)
{
    // features: [c][b_local][i], c = 0..5 basis, 6 = silu
    __shared__ __align__(16) float sfeat[7][BATCH_TILE][NIN];
    __shared__ float sy[BATCH_TILE][OHALF];
    __shared__ int   s_last;

    const int t     = threadIdx.x;
    const int lane  = t & 31;                 // i-pair index: i = 2*lane + ii
    const int w     = t >> 5;                 // warp 0..15 -> o-pair
    const int obase = (blockIdx.x & 1) * OHALF;
    const int b0    = (blockIdx.x >> 1) * BATCH_TILE;
    const int nbl   = min(BATCH_TILE, batch - b0);

    // ---- register-resident coefficients for this thread's 4 j-values ----
    // o = obase + w*2 + q (q=0..1), i = lane*2 + ii
    float cb[2][2][NBASIS];
    float csp[2][2], crs[2][2];
    #pragma unroll
    for (int q = 0; q < 2; q++) {
        #pragma unroll
        for (int ii = 0; ii < 2; ii++) {
            int j = (obase + w * 2 + q) * NIN + lane * 2 + ii;
            #pragma unroll
            for (int c = 0; c < NBASIS; c++) cb[q][ii][c] = __ldg(&c_basis[j * NBASIS + c]);
            csp[q][ii] = __ldg(&c_spl[j]);
            crs[q][ii] = __ldg(&c_res[j]);
        }
    }

    // ---- phase 1: spline basis + silu for nbl x NIN x-values ----
    for (int p = t; p < BATCH_TILE * NIN; p += THREADS) {
        int bl = p >> 6;
        int i  = p & 63;
        int b  = b0 + bl;
        float xv = (b < batch) ? x[b * NIN + i] : 0.0f;

        float kn[NKNOTS];
        #pragma unroll
        for (int m = 0; m < NKNOTS; m++) kn[m] = __ldg(&grid[i * NKNOTS + m]);

        float bs[9];
        #pragma unroll
        for (int m = 0; m < 9; m++)
            bs[m] = (xv >= kn[m] && xv < kn[m + 1]) ? 1.0f : 0.0f;

        #pragma unroll
        for (int K = 1; K <= 3; K++) {
            #pragma unroll
            for (int m = 0; m <= 8 - K; m++) {
                float left  = (xv - kn[m]) / (kn[m + K] - kn[m]);
                float right = (kn[m + K + 1] - xv) / (kn[m + K + 1] - kn[m + 1]);
                bs[m] = left * bs[m] + right * bs[m + 1];
            }
        }
        #pragma unroll
        for (int c = 0; c < NBASIS; c++) sfeat[c][bl][i] = bs[c];
        float sig = 1.0f / (1.0f + __expf(-xv));
        sfeat[6][bl][i] = xv * sig;
    }
    __syncthreads();

    // ---- phase 2: fused spl / y / |spl| accumulation ----
    float acc[2][2];
    acc[0][0] = acc[0][1] = acc[1][0] = acc[1][1] = 0.0f;

    #pragma unroll 1
    for (int bl = 0; bl < nbl; bl++) {
        float2 f[7];
        #pragma unroll
        for (int c = 0; c < 7; c++)
            f[c] = *(const float2*)&sfeat[c][bl][lane * 2];

        float yp[2];
        #pragma unroll
        for (int q = 0; q < 2; q++) {
            float s0 = cb[q][0][0] * f[0].x;
            float s1 = cb[q][1][0] * f[0].y;
            #pragma unroll
            for (int c = 1; c < NBASIS; c++) {
                s0 += cb[q][0][c] * f[c].x;
                s1 += cb[q][1][c] * f[c].y;
            }
            acc[q][0] += fabsf(s0);
            acc[q][1] += fabsf(s1);
            yp[q] = csp[q][0] * s0 + crs[q][0] * f[6].x
                  + csp[q][1] * s1 + crs[q][1] * f[6].y;
        }

        // reduce 2 values over 32 lanes in 9 shfls:
        // butterflies d=16,8,4,2 leave each lane with its bit0-class partial
        // (replicated over bits 1..4); select q by bit1 (reduced => free),
        // final d=1 butterfly completes the sum.
        #pragma unroll
        for (int d = 16; d >= 2; d >>= 1) {
            yp[0] += __shfl_xor_sync(0xffffffffu, yp[0], d);
            yp[1] += __shfl_xor_sync(0xffffffffu, yp[1], d);
        }
        float v = ((lane >> 1) & 1) ? yp[1] : yp[0];
        v += __shfl_xor_sync(0xffffffffu, v, 1);
        if ((lane & ~2u) == 0)                       // lanes 0 (q=0) and 2 (q=1)
            sy[bl][w * 2 + (lane >> 1)] = v;
    }
    __syncthreads();

    // ---- write y (coalesced, 32 floats per row per block) ----
    for (int p = t; p < BATCH_TILE * OHALF; p += THREADS) {
        int bl = p >> 5;
        int o  = p & 31;
        if (bl < nbl)
            y_out[(b0 + bl) * NOUT + obase + o] = sy[bl][o] * (1.0f / NIN);
    }

    // ---- accumulate |spl| partials into L2 (RED, no return) ----
    #pragma unroll
    for (int q = 0; q < 2; q++) {
        #pragma unroll
        for (int ii = 0; ii < 2; ii++) {
            int j = (obase + w * 2 + q) * NIN + lane * 2 + ii;
            atomicAdd(&g_splacc[j], acc[q][ii]);
        }
    }

    // ---- last-block-done: finalize spl_reg + reset accumulators ----
    __threadfence();
    __syncthreads();
    if (t == 0) {
        unsigned r = atomicAdd(&g_ticket, 1u);
        s_last = (r == (unsigned)nblocks - 1) ? 1 : 0;
    }
    __syncthreads();
    if (s_last) {
        for (int j = t; j < NJ; j += THREADS) {
            float v    = __ldcg(&g_splacc[j]);
            float norm = __ldg(&grid[j * NKNOTS + NKNOTS - 1])
                       - __ldg(&grid[j * NKNOTS]) + 1e-5f;
            reg_out[j] = v * inv_batch / norm;
            g_splacc[j] = 0.0f;                  // reset for next graph replay
        }
        __threadfence();
        __syncthreads();
        if (t == 0) atomicExch(&g_ticket, 0u);   // reset ticket for next replay
    }
}

extern "C" void kernel_launch(void* const* d_in, const int* in_sizes, int n_in,
                              void* d_out, int out_size)
{
    const float* x       = (const float*)d_in[0];
    const float* c_basis = (const float*)d_in[1];
    const float* c_spl   = (const float*)d_in[2];
    const float* c_res   = (const float*)d_in[3];
    const float* grid    = (const float*)d_in[4];

    int batch = in_sizes[0] / NIN;

    float* y_out   = (float*)d_out;                 // (batch, 64)
    float* reg_out = y_out + (size_t)batch * NOUT;  // (64, 64)

    int btiles  = (batch + BATCH_TILE - 1) / BATCH_TILE;
    int nblocks = btiles * 2;                       // x2 o-halves
    kan_fused_kernel<<<nblocks, THREADS>>>(x, c_basis, c_spl, c_res, grid,
                                           y_out, reg_out, batch,
                                           1.0f / (float)batch, nblocks);
}

// round 5
// speedup vs baseline: 1.1503x; 1.1503x over previous
#include <cuda_runtime.h>

#define NIN     64
#define NOUT    64
#define NJ      (NIN * NOUT)       // 4096
#define NKNOTS  10
#define NBASIS  6
#define BATCH_TILE 14
#define THREADS 512

// L2-resident accumulator for sum_b |spl[b, j]| + completion ticket.
// Zero-initialized at module load; the last block resets them each launch,
// so every graph replay sees zeros (deterministic).
__device__ float        g_splacc[NJ];
__device__ unsigned int g_ticket;

__global__ __launch_bounds__(THREADS, 1)
void kan_fused_kernel(const float* __restrict__ x,
                      const float* __restrict__ c_basis,
                      const float* __restrict__ c_spl,
                      const float* __restrict__ c_res,
                      const float* __restrict__ grid,
                      float* __restrict__ y_out,
                      float* __restrict__ reg_out,
                      int batch, float inv_batch, int nblocks)
{
    // features: [c][b_local][i], c = 0..5 basis, 6 = silu
    __shared__ __align__(16) float sfeat[7][BATCH_TILE][NIN];
    __shared__ float sy[BATCH_TILE][NOUT];
    __shared__ int   s_last;

    const int t    = threadIdx.x;
    const int lane = t & 31;     // i-pair index: i = 2*lane + ii
    const int oq   = t >> 5;     // o quad: o = oq*4 + q, q = 0..3
    const int b0   = blockIdx.x * BATCH_TILE;
    const int nbl  = min(BATCH_TILE, batch - b0);

    // ---- register-resident coefficients for this thread's 8 j-values ----
    float cb[4][2][NBASIS];
    float csp[4][2], crs[4][2];
    #pragma unroll
    for (int q = 0; q < 4; q++) {
        #pragma unroll
        for (int ii = 0; ii < 2; ii++) {
            int j = (oq * 4 + q) * NIN + lane * 2 + ii;
            #pragma unroll
            for (int c = 0; c < NBASIS; c++) cb[q][ii][c] = __ldg(&c_basis[j * NBASIS + c]);
            csp[q][ii] = __ldg(&c_spl[j]);
            crs[q][ii] = __ldg(&c_res[j]);
        }
    }

    // ---- phase 1: spline basis + silu for nbl x NIN x-values ----
    for (int p = t; p < BATCH_TILE * NIN; p += THREADS) {
        int bl = p >> 6;
        int i  = p & 63;
        int b  = b0 + bl;
        float xv = (b < batch) ? x[b * NIN + i] : 0.0f;

        float kn[NKNOTS];
        #pragma unroll
        for (int m = 0; m < NKNOTS; m++) kn[m] = __ldg(&grid[i * NKNOTS + m]);

        float bs[9];
        #pragma unroll
        for (int m = 0; m < 9; m++)
            bs[m] = (xv >= kn[m] && xv < kn[m + 1]) ? 1.0f : 0.0f;

        #pragma unroll
        for (int K = 1; K <= 3; K++) {
            #pragma unroll
            for (int m = 0; m <= 8 - K; m++) {
                float left  = (xv - kn[m]) / (kn[m + K] - kn[m]);
                float right = (kn[m + K + 1] - xv) / (kn[m + K + 1] - kn[m + 1]);
                bs[m] = left * bs[m] + right * bs[m + 1];
            }
        }
        #pragma unroll
        for (int c = 0; c < NBASIS; c++) sfeat[c][bl][i] = bs[c];
        float sig = 1.0f / (1.0f + __expf(-xv));
        sfeat[6][bl][i] = xv * sig;
    }
    __syncthreads();

    // ---- phase 2: fused spl / y / |spl| accumulation ----
    float acc[4][2];
    #pragma unroll
    for (int q = 0; q < 4; q++) { acc[q][0] = 0.0f; acc[q][1] = 0.0f; }

    #pragma unroll 2
    for (int bl = 0; bl < nbl; bl++) {
        float2 f[7];
        #pragma unroll
        for (int c = 0; c < 7; c++)
            f[c] = *(const float2*)&sfeat[c][bl][lane * 2];

        float yp[4];
        #pragma unroll
        for (int q = 0; q < 4; q++) {
            float s0 = cb[q][0][0] * f[0].x;
            float s1 = cb[q][1][0] * f[0].y;
            #pragma unroll
            for (int c = 1; c < NBASIS; c++) {
                s0 += cb[q][0][c] * f[c].x;
                s1 += cb[q][1][c] * f[c].y;
            }
            acc[q][0] += fabsf(s0);
            acc[q][1] += fabsf(s1);
            yp[q] = csp[q][0] * s0 + crs[q][0] * f[6].x
                  + csp[q][1] * s1 + crs[q][1] * f[6].y;
        }

        // complete 4-value 32-lane reduction in 11 shfls:
        // d=16,8 butterflies reduce bits 3..4; each lane then holds its
        // mod-8-class partial for every q (replicated over bits 3..4), so
        // group g = lane>>3 selects q=g for free; d=4,2,1 butterflies sum
        // the 8 classes within each group -> lanes 0,8,16,24 hold the
        // complete sums for q = 0,1,2,3.
        #pragma unroll
        for (int q = 0; q < 4; q++) {
            yp[q] += __shfl_xor_sync(0xffffffffu, yp[q], 16);
            yp[q] += __shfl_xor_sync(0xffffffffu, yp[q], 8);
        }
        int g = lane >> 3;
        float v = (g == 0) ? yp[0] : (g == 1) ? yp[1] : (g == 2) ? yp[2] : yp[3];
        v += __shfl_xor_sync(0xffffffffu, v, 4);
        v += __shfl_xor_sync(0xffffffffu, v, 2);
        v += __shfl_xor_sync(0xffffffffu, v, 1);
        if ((lane & 7) == 0)
            sy[bl][oq * 4 + g] = v;
    }
    __syncthreads();

    // ---- write y (coalesced) ----
    for (int p = t; p < BATCH_TILE * NOUT; p += THREADS) {
        int bl = p >> 6;
        int o  = p & 63;
        if (bl < nbl)
            y_out[(b0 + bl) * NOUT + o] = sy[bl][o] * (1.0f / NIN);
    }

    // ---- accumulate |spl| partials into L2 ----
    #pragma unroll
    for (int q = 0; q < 4; q++) {
        #pragma unroll
        for (int ii = 0; ii < 2; ii++) {
            int j = (oq * 4 + q) * NIN + lane * 2 + ii;
            atomicAdd(&g_splacc[j], acc[q][ii]);
        }
    }

    // ---- last-block-done: finalize spl_reg + reset accumulators ----
    __threadfence();
    __syncthreads();
    if (t == 0) {
        unsigned r = atomicAdd(&g_ticket, 1u);
        s_last = (r == (unsigned)nblocks - 1) ? 1 : 0;
    }
    __syncthreads();
    if (s_last) {
        for (int j = t; j < NJ; j += THREADS) {
            float v    = __ldcg(&g_splacc[j]);
            float norm = __ldg(&grid[j * NKNOTS + NKNOTS - 1])
                       - __ldg(&grid[j * NKNOTS]) + 1e-5f;
            reg_out[j] = v * inv_batch / norm;
            g_splacc[j] = 0.0f;                  // reset for next graph replay
        }
        __threadfence();
        __syncthreads();
        if (t == 0) atomicExch(&g_ticket, 0u);   // reset ticket for next replay
    }
}

extern "C" void kernel_launch(void* const* d_in, const int* in_sizes, int n_in,
                              void* d_out, int out_size)
{
    const float* x       = (const float*)d_in[0];
    const float* c_basis = (const float*)d_in[1];
    const float* c_spl   = (const float*)d_in[2];
    const float* c_res   = (const float*)d_in[3];
    const float* grid    = (const float*)d_in[4];

    int batch = in_sizes[0] / NIN;

    float* y_out   = (float*)d_out;                 // (batch, 64)
    float* reg_out = y_out + (size_t)batch * NOUT;  // (64, 64)

    int nblocks = (batch + BATCH_TILE - 1) / BATCH_TILE;
    kan_fused_kernel<<<nblocks, THREADS>>>(x, c_basis, c_spl, c_res, grid,
                                           y_out, reg_out, batch,
                                           1.0f / (float)batch, nblocks);
}

// round 6
// speedup vs baseline: 1.2653x; 1.1000x over previous
#include <cuda_runtime.h>

#define NIN     64
#define NOUT    64
#define NJ      (NIN * NOUT)       // 4096
#define NKNOTS  10
#define NBASIS  6
#define BATCH_TILE 14
#define THREADS 512

// dynamic shared layout (bytes)
#define SFEAT_FLOATS  (7 * BATCH_TILE * NIN)                 // 6272 floats
#define SYPART_OFF    ((SFEAT_FLOATS * 4 + 15) & ~15)        // 16B aligned
#define SYPART_BYTES  (BATCH_TILE * 16 * 32 * 16)            // float4[14][16][32] = 114688
#define SMEM_TOTAL    (SYPART_OFF + SYPART_BYTES)

// L2-resident accumulator for sum_b |spl[b, j]| + completion ticket.
// Zero-initialized at module load; the last block resets them each launch,
// so every graph replay sees zeros (deterministic).
__device__ float        g_splacc[NJ];
__device__ unsigned int g_ticket;

__global__ __launch_bounds__(THREADS, 1)
void kan_fused_kernel(const float* __restrict__ x,
                      const float* __restrict__ c_basis,
                      const float* __restrict__ c_spl,
                      const float* __restrict__ c_res,
                      const float* __restrict__ grid,
                      float* __restrict__ y_out,
                      float* __restrict__ reg_out,
                      int batch, float inv_batch, int nblocks)
{
    extern __shared__ __align__(16) char smem_raw[];
    // features: [c][b_local][i], c = 0..5 basis, 6 = silu
    float (*sfeat)[BATCH_TILE][NIN] = (float (*)[BATCH_TILE][NIN])smem_raw;
    // y partials: [bl][oq][lane] as float4 (q = 0..3 packed)
    float4 (*sypart)[16][32] = (float4 (*)[16][32])(smem_raw + SYPART_OFF);
    __shared__ int s_last;

    const int t    = threadIdx.x;
    const int lane = t & 31;     // i-pair index: i = 2*lane + ii
    const int oq   = t >> 5;     // o quad: o = oq*4 + q, q = 0..3
    const int b0   = blockIdx.x * BATCH_TILE;
    const int nbl  = min(BATCH_TILE, batch - b0);

    // ---- register-resident coefficients for this thread's 8 j-values ----
    float cb[4][2][NBASIS];
    float csp[4][2], crs[4][2];
    #pragma unroll
    for (int q = 0; q < 4; q++) {
        #pragma unroll
        for (int ii = 0; ii < 2; ii++) {
            int j = (oq * 4 + q) * NIN + lane * 2 + ii;
            #pragma unroll
            for (int c = 0; c < NBASIS; c++) cb[q][ii][c] = __ldg(&c_basis[j * NBASIS + c]);
            csp[q][ii] = __ldg(&c_spl[j]);
            crs[q][ii] = __ldg(&c_res[j]);
        }
    }

    // ---- phase 1: spline basis + silu for nbl x NIN x-values ----
    for (int p = t; p < BATCH_TILE * NIN; p += THREADS) {
        int bl = p >> 6;
        int i  = p & 63;
        int b  = b0 + bl;
        float xv = (b < batch) ? x[b * NIN + i] : 0.0f;

        float kn[NKNOTS];
        #pragma unroll
        for (int m = 0; m < NKNOTS; m++) kn[m] = __ldg(&grid[i * NKNOTS + m]);

        float bs[9];
        #pragma unroll
        for (int m = 0; m < 9; m++)
            bs[m] = (xv >= kn[m] && xv < kn[m + 1]) ? 1.0f : 0.0f;

        #pragma unroll
        for (int K = 1; K <= 3; K++) {
            #pragma unroll
            for (int m = 0; m <= 8 - K; m++) {
                float left  = (xv - kn[m]) / (kn[m + K] - kn[m]);
                float right = (kn[m + K + 1] - xv) / (kn[m + K + 1] - kn[m + 1]);
                bs[m] = left * bs[m] + right * bs[m + 1];
            }
        }
        #pragma unroll
        for (int c = 0; c < NBASIS; c++) sfeat[c][bl][i] = bs[c];
        float sig = 1.0f / (1.0f + __expf(-xv));
        sfeat[6][bl][i] = xv * sig;
    }
    __syncthreads();

    // ---- phase 2: fused spl / y-partial / |spl| accumulation (NO shfl) ----
    float acc[4][2];
    #pragma unroll
    for (int q = 0; q < 4; q++) { acc[q][0] = 0.0f; acc[q][1] = 0.0f; }

    #pragma unroll 2
    for (int bl = 0; bl < nbl; bl++) {
        float2 f[7];
        #pragma unroll
        for (int c = 0; c < 7; c++)
            f[c] = *(const float2*)&sfeat[c][bl][lane * 2];

        float4 yp;
        float* ypp = (float*)&yp;
        #pragma unroll
        for (int q = 0; q < 4; q++) {
            float s0 = cb[q][0][0] * f[0].x;
            float s1 = cb[q][1][0] * f[0].y;
            #pragma unroll
            for (int c = 1; c < NBASIS; c++) {
                s0 += cb[q][0][c] * f[c].x;
                s1 += cb[q][1][c] * f[c].y;
            }
            acc[q][0] += fabsf(s0);
            acc[q][1] += fabsf(s1);
            ypp[q] = csp[q][0] * s0 + crs[q][0] * f[6].x
                   + csp[q][1] * s1 + crs[q][1] * f[6].y;
        }
        // fire-and-forget: 512B contiguous per warp, conflict-free
        sypart[bl][oq][lane] = yp;
    }
    __syncthreads();

    // ---- reduce lane dimension, write y directly (STG.128) ----
    for (int p = t; p < BATCH_TILE * 16; p += THREADS) {
        int bl = p >> 4;
        int oqr = p & 15;
        if (bl < nbl) {
            float4 s = make_float4(0.f, 0.f, 0.f, 0.f);
            #pragma unroll
            for (int l = 0; l < 32; l++) {
                int ls = (l + lane) & 31;          // stagger to avoid bank conflicts
                float4 v = sypart[bl][oqr][ls];
                s.x += v.x; s.y += v.y; s.z += v.z; s.w += v.w;
            }
            const float sc = 1.0f / NIN;
            s.x *= sc; s.y *= sc; s.z *= sc; s.w *= sc;
            *(float4*)&y_out[(size_t)(b0 + bl) * NOUT + oqr * 4] = s;
        }
    }

    // ---- accumulate |spl| partials into L2 ----
    #pragma unroll
    for (int q = 0; q < 4; q++) {
        #pragma unroll
        for (int ii = 0; ii < 2; ii++) {
            int j = (oq * 4 + q) * NIN + lane * 2 + ii;
            atomicAdd(&g_splacc[j], acc[q][ii]);
        }
    }

    // ---- last-block-done: finalize spl_reg + reset accumulators ----
    __threadfence();
    __syncthreads();
    if (t == 0) {
        unsigned r = atomicAdd(&g_ticket, 1u);
        s_last = (r == (unsigned)nblocks - 1) ? 1 : 0;
    }
    __syncthreads();
    if (s_last) {
        for (int j = t; j < NJ; j += THREADS) {
            float v    = __ldcg(&g_splacc[j]);
            float norm = __ldg(&grid[j * NKNOTS + NKNOTS - 1])
                       - __ldg(&grid[j * NKNOTS]) + 1e-5f;
            reg_out[j] = v * inv_batch / norm;
            g_splacc[j] = 0.0f;                  // reset for next graph replay
        }
        __threadfence();
        __syncthreads();
        if (t == 0) atomicExch(&g_ticket, 0u);   // reset ticket for next replay
    }
}

extern "C" void kernel_launch(void* const* d_in, const int* in_sizes, int n_in,
                              void* d_out, int out_size)
{
    const float* x       = (const float*)d_in[0];
    const float* c_basis = (const float*)d_in[1];
    const float* c_spl   = (const float*)d_in[2];
    const float* c_res   = (const float*)d_in[3];
    const float* grid    = (const float*)d_in[4];

    int batch = in_sizes[0] / NIN;

    float* y_out   = (float*)d_out;                 // (batch, 64)
    float* reg_out = y_out + (size_t)batch * NOUT;  // (64, 64)

    cudaFuncSetAttribute(kan_fused_kernel,
                         cudaFuncAttributeMaxDynamicSharedMemorySize, SMEM_TOTAL);

    int nblocks = (batch + BATCH_TILE - 1) / BATCH_TILE;
    kan_fused_kernel<<<nblocks, THREADS, SMEM_TOTAL>>>(x, c_basis, c_spl, c_res, grid,
                                                       y_out, reg_out, batch,
                                                       1.0f / (float)batch, nblocks);
}

// round 7
// speedup vs baseline: 1.2670x; 1.0014x over previous
#include <cuda_runtime.h>

#define NIN     64
#define NOUT    64
#define NJ      (NIN * NOUT)       // 4096
#define NKNOTS  10
#define NBASIS  6
#define NRCP    24                 // K=1: m0..8 (9), K=2: m0..7 (8), K=3: m0..6 (7)
#define BATCH_TILE 14
#define THREADS 512

// ---- dynamic shared layout (bytes) ----
#define SFEAT_BYTES   (7 * BATCH_TILE * NIN * 4)            // 25088
#define SGRID_OFF     SFEAT_BYTES
#define SGRID_BYTES   (NKNOTS * NIN * 4)                    // 2560
#define SRCP_OFF      (SGRID_OFF + SGRID_BYTES)
#define SRCP_BYTES    (NRCP * NIN * 4)                      // 6144
#define SYPART_OFF    (SRCP_OFF + SRCP_BYTES)
#define SYPART_BYTES  (BATCH_TILE * 16 * 32 * 16)           // 114688
#define SPART_OFF     (SYPART_OFF + SYPART_BYTES)
#define SPART_BYTES   (BATCH_TILE * 16 * 2 * 16)            // 7168
#define SMEM_TOTAL    (SPART_OFF + SPART_BYTES)             // ~152KB

// L2-resident accumulator for sum_b |spl[b, j]| + completion ticket.
// Zero at module load; last block resets each launch (graph-replay safe).
__device__ float        g_splacc[NJ];
__device__ unsigned int g_ticket;

struct Smem {
    float  (*sfeat)[BATCH_TILE][NIN];   // [7][bl][i]
    float  (*sgrid)[NIN];               // [m][i]
    float  (*srcp)[NIN];                // [e][i]
    float4 (*sypart)[16][32];           // [bl][oq][lane]
    float4 (*spart)[2];                 // [item][half]
};

template <bool FULL>
__device__ __forceinline__
void phase2(const Smem& S, int nbl, int lane, int oq,
            const float cb[4][2][NBASIS], const float csp[4][2],
            const float crs[4][2], float acc[4][2])
{
    const int NB = FULL ? BATCH_TILE : nbl;
    #pragma unroll
    for (int bl = 0; bl < (FULL ? BATCH_TILE : BATCH_TILE); bl++) {
        if (!FULL && bl >= NB) break;
        float2 f[7];
        #pragma unroll
        for (int c = 0; c < 7; c++)
            f[c] = *(const float2*)&S.sfeat[c][bl][lane * 2];

        float4 yp;
        float* ypp = (float*)&yp;
        #pragma unroll
        for (int q = 0; q < 4; q++) {
            float s0 = cb[q][0][0] * f[0].x;
            float s1 = cb[q][1][0] * f[0].y;
            #pragma unroll
            for (int c = 1; c < NBASIS; c++) {
                s0 += cb[q][0][c] * f[c].x;
                s1 += cb[q][1][c] * f[c].y;
            }
            acc[q][0] += fabsf(s0);
            acc[q][1] += fabsf(s1);
            ypp[q] = csp[q][0] * s0 + crs[q][0] * f[6].x
                   + csp[q][1] * s1 + crs[q][1] * f[6].y;
        }
        S.sypart[bl][oq][lane] = yp;    // fire-and-forget
    }
}

__global__ __launch_bounds__(THREADS, 1)
void kan_fused_kernel(const float* __restrict__ x,
                      const float* __restrict__ c_basis,
                      const float* __restrict__ c_spl,
                      const float* __restrict__ c_res,
                      const float* __restrict__ grid,
                      float* __restrict__ y_out,
                      float* __restrict__ reg_out,
                      int batch, float inv_batch, int nblocks)
{
    extern __shared__ __align__(16) char smem_raw[];
    Smem S;
    S.sfeat  = (float  (*)[BATCH_TILE][NIN])(smem_raw);
    S.sgrid  = (float  (*)[NIN])(smem_raw + SGRID_OFF);
    S.srcp   = (float  (*)[NIN])(smem_raw + SRCP_OFF);
    S.sypart = (float4 (*)[16][32])(smem_raw + SYPART_OFF);
    S.spart  = (float4 (*)[2])(smem_raw + SPART_OFF);
    __shared__ int s_last;

    const int t    = threadIdx.x;
    const int lane = t & 31;     // i-pair index: i = 2*lane + ii
    const int oq   = t >> 5;     // o quad: o = oq*4 + q
    const int b0   = blockIdx.x * BATCH_TILE;
    const int nbl  = min(BATCH_TILE, batch - b0);

    // ---- phase 0a: stage knots + reciprocal tables in shared ----
    for (int p = t; p < NKNOTS * NIN; p += THREADS) {
        int i = p / NKNOTS, m = p % NKNOTS;          // coalesced-ish global read
        S.sgrid[m][i] = __ldg(&grid[i * NKNOTS + m]);
    }
    for (int p = t; p < NRCP * NIN; p += THREADS) {
        int i = p & 63, e = p >> 6;
        int K = (e < 9) ? 1 : (e < 17) ? 2 : 3;
        int m = (e < 9) ? e : (e < 17) ? e - 9 : e - 17;
        float d = __ldg(&grid[i * NKNOTS + m + K]) - __ldg(&grid[i * NKNOTS + m]);
        S.srcp[e][i] = 1.0f / d;
    }

    // ---- register-resident coefficients for this thread's 8 j-values ----
    float cb[4][2][NBASIS];
    float csp[4][2], crs[4][2];
    #pragma unroll
    for (int q = 0; q < 4; q++) {
        #pragma unroll
        for (int ii = 0; ii < 2; ii++) {
            int j = (oq * 4 + q) * NIN + lane * 2 + ii;
            #pragma unroll
            for (int c = 0; c < NBASIS; c++) cb[q][ii][c] = __ldg(&c_basis[j * NBASIS + c]);
            csp[q][ii] = __ldg(&c_spl[j]);
            crs[q][ii] = __ldg(&c_res[j]);
        }
    }
    __syncthreads();

    // ---- phase 1: division-free basis + silu ----
    for (int p = t; p < BATCH_TILE * NIN; p += THREADS) {
        int bl = p >> 6;
        int i  = p & 63;
        int b  = b0 + bl;
        float xv = (b < batch) ? x[b * NIN + i] : 0.0f;

        float kn[NKNOTS];
        #pragma unroll
        for (int m = 0; m < NKNOTS; m++) kn[m] = S.sgrid[m][i];
        float rc[NRCP];
        #pragma unroll
        for (int e = 0; e < NRCP; e++) rc[e] = S.srcp[e][i];

        float bs[9];
        #pragma unroll
        for (int m = 0; m < 9; m++)
            bs[m] = (xv >= kn[m] && xv < kn[m + 1]) ? 1.0f : 0.0f;

        #pragma unroll
        for (int K = 1; K <= 3; K++) {
            const int off = (K == 1) ? 0 : (K == 2) ? 9 : 17;
            #pragma unroll
            for (int m = 0; m <= 8 - K; m++) {
                float left  = (xv - kn[m]) * rc[off + m];
                float right = (kn[m + K + 1] - xv) * rc[off + m + 1];
                bs[m] = left * bs[m] + right * bs[m + 1];
            }
        }
        #pragma unroll
        for (int c = 0; c < NBASIS; c++) S.sfeat[c][bl][i] = bs[c];
        float sig = 1.0f / (1.0f + __expf(-xv));
        S.sfeat[6][bl][i] = xv * sig;
    }
    __syncthreads();

    // ---- phase 2: fused spl / y-partial / |spl| (no shfl) ----
    float acc[4][2];
    #pragma unroll
    for (int q = 0; q < 4; q++) { acc[q][0] = 0.0f; acc[q][1] = 0.0f; }

    if (nbl == BATCH_TILE) phase2<true >(S, nbl, lane, oq, cb, csp, crs, acc);
    else                   phase2<false>(S, nbl, lane, oq, cb, csp, crs, acc);
    __syncthreads();

    // ---- epilogue: reduce lane dim (2 threads per output float4) ----
    {
        int p = t;                       // items: [bl][oqr] x half
        int item = p >> 1, half = p & 1;
        int bl = item >> 4, oqr = item & 15;
        if (p < BATCH_TILE * 16 * 2 && bl < nbl) {
            float4 s = make_float4(0.f, 0.f, 0.f, 0.f);
            int base = half * 16;
            #pragma unroll
            for (int k = 0; k < 16; k++) {
                int ls = base + ((k + (t & 15)) & 15);   // stagger
                float4 v = S.sypart[bl][oqr][ls];
                s.x += v.x; s.y += v.y; s.z += v.z; s.w += v.w;
            }
            S.spart[item][half] = s;
        }
    }
    __syncthreads();
    {
        int item = t;
        int bl = item >> 4, oqr = item & 15;
        if (item < BATCH_TILE * 16 && bl < nbl) {
            float4 a = S.spart[item][0];
            float4 b = S.spart[item][1];
            const float sc = 1.0f / NIN;
            a.x = (a.x + b.x) * sc; a.y = (a.y + b.y) * sc;
            a.z = (a.z + b.z) * sc; a.w = (a.w + b.w) * sc;
            *(float4*)&y_out[(size_t)(b0 + bl) * NOUT + oqr * 4] = a;
        }
    }

    // ---- accumulate |spl| partials into L2 ----
    #pragma unroll
    for (int q = 0; q < 4; q++) {
        #pragma unroll
        for (int ii = 0; ii < 2; ii++) {
            int j = (oq * 4 + q) * NIN + lane * 2 + ii;
            atomicAdd(&g_splacc[j], acc[q][ii]);
        }
    }

    // ---- last-block-done: finalize spl_reg + reset accumulators ----
    __threadfence();
    __syncthreads();
    if (t == 0) {
        unsigned r = atomicAdd(&g_ticket, 1u);
        s_last = (r == (unsigned)nblocks - 1) ? 1 : 0;
    }
    __syncthreads();
    if (s_last) {
        for (int j = t; j < NJ; j += THREADS) {
            float v    = __ldcg(&g_splacc[j]);
            float norm = __ldg(&grid[j * NKNOTS + NKNOTS - 1])
                       - __ldg(&grid[j * NKNOTS]) + 1e-5f;
            reg_out[j] = v * inv_batch / norm;
            g_splacc[j] = 0.0f;                  // reset for next replay
        }
        __threadfence();
        __syncthreads();
        if (t == 0) atomicExch(&g_ticket, 0u);
    }
}

extern "C" void kernel_launch(void* const* d_in, const int* in_sizes, int n_in,
                              void* d_out, int out_size)
{
    const float* x       = (const float*)d_in[0];
    const float* c_basis = (const float*)d_in[1];
    const float* c_spl   = (const float*)d_in[2];
    const float* c_res   = (const float*)d_in[3];
    const float* grid    = (const float*)d_in[4];

    int batch = in_sizes[0] / NIN;

    float* y_out   = (float*)d_out;                 // (batch, 64)
    float* reg_out = y_out + (size_t)batch * NOUT;  // (64, 64)

    cudaFuncSetAttribute(kan_fused_kernel,
                         cudaFuncAttributeMaxDynamicSharedMemorySize, SMEM_TOTAL);

    int nblocks = (batch + BATCH_TILE - 1) / BATCH_TILE;
    kan_fused_kernel<<<nblocks, THREADS, SMEM_TOTAL>>>(x, c_basis, c_spl, c_res, grid,
                                                       y_out, reg_out, batch,
                                                       1.0f / (float)batch, nblocks);
}

// round 8
// speedup vs baseline: 1.5734x; 1.2418x over previous
#include <cuda_runtime.h>

#define NIN     64
#define NOUT    64
#define NJ      (NIN * NOUT)       // 4096
#define NKNOTS  10
#define NBASIS  6
#define NRCP    24
#define BATCH_TILE 14
#define THREADS 512

// ---- dynamic shared layout (bytes) ----
#define SFEAT_BYTES   (7 * BATCH_TILE * NIN * 4)            // 25088
#define SGRID_OFF     SFEAT_BYTES
#define SGRID_BYTES   (NKNOTS * NIN * 4)
#define SRCP_OFF      (SGRID_OFF + SGRID_BYTES)
#define SRCP_BYTES    (NRCP * NIN * 4)
#define SYPART_OFF    (SRCP_OFF + SRCP_BYTES)
#define SYPART_BYTES  (BATCH_TILE * 16 * 32 * 16)
#define SPART_OFF     (SYPART_OFF + SYPART_BYTES)
#define SPART_BYTES   (BATCH_TILE * 16 * 2 * 16)
#define SMEM_TOTAL    (SPART_OFF + SPART_BYTES)

typedef unsigned long long ull;
__device__ __forceinline__ ull pack2(float lo, float hi) {
    ull r; asm("mov.b64 %0, {%1, %2};" : "=l"(r) : "f"(lo), "f"(hi)); return r;
}
#define FMA2(d,a,b,c) asm("fma.rn.f32x2 %0, %1, %2, %3;" : "=l"(d) : "l"(a), "l"(b), "l"(c))
#define MUL2(d,a,b)   asm("mul.rn.f32x2 %0, %1, %2;"     : "=l"(d) : "l"(a), "l"(b))
#define UNPK(lo,hi,p) asm("mov.b64 {%0, %1}, %2;" : "=f"(lo), "=f"(hi) : "l"(p))

// L2-resident accumulator + scale table + ticket. Zero at module load;
// last block resets splacc/ticket each launch (graph-replay safe).
// g_invnorm is recomputed identically every launch (deterministic).
__device__ __align__(16) float g_splacc[NJ];
__device__ __align__(16) float g_invnorm[NJ];
__device__ unsigned int g_ticket;

struct Smem {
    float  (*sfeat)[BATCH_TILE][NIN];
    float  (*sgrid)[NIN];
    float  (*srcp)[NIN];
    float4 (*sypart)[16][32];
    float4 (*spart)[2];
};

template <bool FULL>
__device__ __forceinline__
void phase2(const Smem& S, int nbl, int lane, int oq,
            const ull cb01[4][NBASIS], const ull csp01[4],
            const ull crs01[4], float acc[4][2])
{
    #pragma unroll
    for (int bl = 0; bl < BATCH_TILE; bl++) {
        if (!FULL && bl >= nbl) break;
        ull f01[7];
        #pragma unroll
        for (int c = 0; c < 7; c++)
            f01[c] = *(const ull*)&S.sfeat[c][bl][lane * 2];

        float4 yp;
        float* ypp = (float*)&yp;
        #pragma unroll
        for (int q = 0; q < 4; q++) {
            ull s01;
            MUL2(s01, cb01[q][0], f01[0]);
            #pragma unroll
            for (int c = 1; c < NBASIS; c++)
                FMA2(s01, cb01[q][c], f01[c], s01);
            float s0, s1; UNPK(s0, s1, s01);
            acc[q][0] += fabsf(s0);
            acc[q][1] += fabsf(s1);
            ull t01;
            MUL2(t01, csp01[q], s01);
            FMA2(t01, crs01[q], f01[6], t01);
            float t0, t1; UNPK(t0, t1, t01);
            ypp[q] = t0 + t1;
        }
        S.sypart[bl][oq][lane] = yp;    // fire-and-forget
    }
}

__global__ __launch_bounds__(THREADS, 1)
void kan_fused_kernel(const float* __restrict__ x,
                      const float* __restrict__ c_basis,
                      const float* __restrict__ c_spl,
                      const float* __restrict__ c_res,
                      const float* __restrict__ grid,
                      float* __restrict__ y_out,
                      float* __restrict__ reg_out,
                      int batch, float inv_batch, int nblocks)
{
    extern __shared__ __align__(16) char smem_raw[];
    Smem S;
    S.sfeat  = (float  (*)[BATCH_TILE][NIN])(smem_raw);
    S.sgrid  = (float  (*)[NIN])(smem_raw + SGRID_OFF);
    S.srcp   = (float  (*)[NIN])(smem_raw + SRCP_OFF);
    S.sypart = (float4 (*)[16][32])(smem_raw + SYPART_OFF);
    S.spart  = (float4 (*)[2])(smem_raw + SPART_OFF);
    __shared__ int s_last;

    const int t    = threadIdx.x;
    const int lane = t & 31;
    const int oq   = t >> 5;
    const int b0   = blockIdx.x * BATCH_TILE;
    const int nbl  = min(BATCH_TILE, batch - b0);

    // ---- phase 0a: this block's slice of g_invnorm (folding inv_batch) ----
    {
        int span = (NJ + nblocks - 1) / nblocks;
        int j0 = blockIdx.x * span;
        int j1 = min(j0 + span, NJ);
        for (int jj = j0 + t; jj < j1; jj += THREADS) {
            float hi = __ldg(&grid[jj * NKNOTS + NKNOTS - 1]);
            float lo = __ldg(&grid[jj * NKNOTS]);
            g_invnorm[jj] = inv_batch / (hi - lo + 1e-5f);
        }
    }

    // ---- phase 0b: stage knots + reciprocal tables in shared ----
    for (int p = t; p < NKNOTS * NIN; p += THREADS) {
        int i = p / NKNOTS, m = p % NKNOTS;
        S.sgrid[m][i] = __ldg(&grid[i * NKNOTS + m]);
    }
    for (int p = t; p < NRCP * NIN; p += THREADS) {
        int i = p & 63, e = p >> 6;
        int K = (e < 9) ? 1 : (e < 17) ? 2 : 3;
        int m = (e < 9) ? e : (e < 17) ? e - 9 : e - 17;
        float d = __ldg(&grid[i * NKNOTS + m + K]) - __ldg(&grid[i * NKNOTS + m]);
        S.srcp[e][i] = 1.0f / d;
    }

    // ---- register-resident packed coefficients (8 j per thread) ----
    ull cb01[4][NBASIS], csp01[4], crs01[4];
    #pragma unroll
    for (int q = 0; q < 4; q++) {
        int j0 = (oq * 4 + q) * NIN + lane * 2;
        #pragma unroll
        for (int c = 0; c < NBASIS; c++)
            cb01[q][c] = pack2(__ldg(&c_basis[j0 * NBASIS + c]),
                               __ldg(&c_basis[(j0 + 1) * NBASIS + c]));
        csp01[q] = pack2(__ldg(&c_spl[j0]), __ldg(&c_spl[j0 + 1]));
        crs01[q] = pack2(__ldg(&c_res[j0]), __ldg(&c_res[j0 + 1]));
    }
    __syncthreads();

    // ---- phase 1: division-free basis + silu ----
    for (int p = t; p < BATCH_TILE * NIN; p += THREADS) {
        int bl = p >> 6;
        int i  = p & 63;
        int b  = b0 + bl;
        float xv = (b < batch) ? x[b * NIN + i] : 0.0f;

        float kn[NKNOTS];
        #pragma unroll
        for (int m = 0; m < NKNOTS; m++) kn[m] = S.sgrid[m][i];
        float rc[NRCP];
        #pragma unroll
        for (int e = 0; e < NRCP; e++) rc[e] = S.srcp[e][i];

        float bs[9];
        #pragma unroll
        for (int m = 0; m < 9; m++)
            bs[m] = (xv >= kn[m] && xv < kn[m + 1]) ? 1.0f : 0.0f;

        #pragma unroll
        for (int K = 1; K <= 3; K++) {
            const int off = (K == 1) ? 0 : (K == 2) ? 9 : 17;
            #pragma unroll
            for (int m = 0; m <= 8 - K; m++) {
                float left  = (xv - kn[m]) * rc[off + m];
                float right = (kn[m + K + 1] - xv) * rc[off + m + 1];
                bs[m] = left * bs[m] + right * bs[m + 1];
            }
        }
        #pragma unroll
        for (int c = 0; c < NBASIS; c++) S.sfeat[c][bl][i] = bs[c];
        float sig = 1.0f / (1.0f + __expf(-xv));
        S.sfeat[6][bl][i] = xv * sig;
    }
    __syncthreads();

    // ---- phase 2: packed-FMA spl / y-partial / |spl| ----
    float acc[4][2];
    #pragma unroll
    for (int q = 0; q < 4; q++) { acc[q][0] = 0.0f; acc[q][1] = 0.0f; }

    if (nbl == BATCH_TILE) phase2<true >(S, nbl, lane, oq, cb01, csp01, crs01, acc);
    else                   phase2<false>(S, nbl, lane, oq, cb01, csp01, crs01, acc);

    // ---- issue atomics NOW so L2 drain overlaps the epilogue ----
    #pragma unroll
    for (int q = 0; q < 4; q++) {
        #pragma unroll
        for (int ii = 0; ii < 2; ii++) {
            int j = (oq * 4 + q) * NIN + lane * 2 + ii;
            atomicAdd(&g_splacc[j], acc[q][ii]);
        }
    }
    __syncthreads();

    // ---- epilogue: reduce lane dim (2 threads per output float4) ----
    {
        int item = t >> 1, half = t & 1;
        int bl = item >> 4, oqr = item & 15;
        if (t < BATCH_TILE * 16 * 2 && bl < nbl) {
            float4 s = make_float4(0.f, 0.f, 0.f, 0.f);
            int base = half * 16;
            #pragma unroll
            for (int k = 0; k < 16; k++) {
                int ls = base + ((k + (t & 15)) & 15);
                float4 v = S.sypart[bl][oqr][ls];
                s.x += v.x; s.y += v.y; s.z += v.z; s.w += v.w;
            }
            S.spart[item][half] = s;
        }
    }
    __syncthreads();
    {
        int item = t;
        int bl = item >> 4, oqr = item & 15;
        if (item < BATCH_TILE * 16 && bl < nbl) {
            float4 a = S.spart[item][0];
            float4 b = S.spart[item][1];
            const float sc = 1.0f / NIN;
            a.x = (a.x + b.x) * sc; a.y = (a.y + b.y) * sc;
            a.z = (a.z + b.z) * sc; a.w = (a.w + b.w) * sc;
            *(float4*)&y_out[(size_t)(b0 + bl) * NOUT + oqr * 4] = a;
        }
    }

    // ---- last-block-done: finalize spl_reg (pure fp32x4 multiply) ----
    __threadfence();
    __syncthreads();
    if (t == 0) {
        unsigned r = atomicAdd(&g_ticket, 1u);
        s_last = (r == (unsigned)nblocks - 1) ? 1 : 0;
    }
    __syncthreads();
    if (s_last) {
        float4* accv = (float4*)g_splacc;
        float4* invv = (float4*)g_invnorm;
        float4* outv = (float4*)reg_out;
        #pragma unroll
        for (int j4 = t; j4 < NJ / 4; j4 += THREADS) {
            float4 v = __ldcg(&accv[j4]);
            float4 w = __ldcg(&invv[j4]);
            v.x *= w.x; v.y *= w.y; v.z *= w.z; v.w *= w.w;
            outv[j4] = v;
            accv[j4] = make_float4(0.f, 0.f, 0.f, 0.f);   // reset for next replay
        }
        __threadfence();
        __syncthreads();
        if (t == 0) atomicExch(&g_ticket, 0u);
    }
}

extern "C" void kernel_launch(void* const* d_in, const int* in_sizes, int n_in,
                              void* d_out, int out_size)
{
    const float* x       = (const float*)d_in[0];
    const float* c_basis = (const float*)d_in[1];
    const float* c_spl   = (const float*)d_in[2];
    const float* c_res   = (const float*)d_in[3];
    const float* grid    = (const float*)d_in[4];

    int batch = in_sizes[0] / NIN;

    float* y_out   = (float*)d_out;                 // (batch, 64)
    float* reg_out = y_out + (size_t)batch * NOUT;  // (64, 64)

    cudaFuncSetAttribute(kan_fused_kernel,
                         cudaFuncAttributeMaxDynamicSharedMemorySize, SMEM_TOTAL);

    int nblocks = (batch + BATCH_TILE - 1) / BATCH_TILE;
    kan_fused_kernel<<<nblocks, THREADS, SMEM_TOTAL>>>(x, c_basis, c_spl, c_res, grid,
                                                       y_out, reg_out, batch,
                                                       1.0f / (float)batch, nblocks);
}